// round 2
// baseline (speedup 1.0000x reference)
#include <cuda_runtime.h>
#include <cstdint>

// ---------------------------------------------------------------------------
// KAN-Mixer fused kernel (round 1): mma.sync tf32, fused 2-layer per row-tile.
//
// Row m = b*C + c  (b in [0,64), c in [0,768)).  xT[m,p] = x[b,p,c].
// Layer1: h[m,j] = sum_{k<1764} feat1(m,k) * W1[j,k] + b1[j]     (j < 384)
//   k < 1568 : feat = exp(-(((x+1)*3.5) - q)^2),  p = k>>3, q = k&7
//   k < 1764 : feat = silu(x[p]),                 p = k-1568
// Layer2: o[m,p] = sum_{k<3456} feat2(m,k) * W2[p,k] + b2[p]     (p < 196)
//   k < 3072 : basis of h[j], j = k>>3, q = k&7 ;  else silu(h[k-3072])
// out[b,p,c] = o[m,p] + x[b,p,c]
// ---------------------------------------------------------------------------

#define BQ   64
#define PP   196
#define CC   768
#define HSZ  384

#define K1P  1792          // 1764 padded to mult of 64
#define KS1  (K1P/8)       // 224 k8-steps
#define NT1  (HSZ/8)       // 48 n8-tiles

#define K2   3456          // 3072 + 384, already mult of 32
#define KS2  (K2/8)        // 432
#define N2P  224           // 196 padded to mult of 32 (8 warps * 7 tiles * ... )
#define NT2  (N2P/8)       // 28

#define KC   32            // k-chunk per iteration
#define KSL  (KC/8)        // 4 k8-steps per chunk
#define MTILE 64           // rows per CTA
#define NTHREADS 256

#define L2E 1.4426950408889634f

// fragment-ordered weights: index = ((ks*NT + nt)*32 + t)*2 + r
__device__ float g_W1[(size_t)KS1 * NT1 * 64];   // 2.75 MB
__device__ float g_W2[(size_t)KS2 * NT2 * 64];   // 3.10 MB

static __device__ __forceinline__ float ex2f(float z) {
    float r; asm("ex2.approx.ftz.f32 %0, %1;" : "=f"(r) : "f"(z)); return r;
}
static __device__ __forceinline__ float rcpf(float z) {
    float r; asm("rcp.approx.ftz.f32 %0, %1;" : "=f"(r) : "f"(z)); return r;
}
static __device__ __forceinline__ unsigned tf32r(float v) {
    unsigned u; asm("cvt.rna.tf32.f32 %0, %1;" : "=r"(u) : "f"(v)); return u;
}
static __device__ __forceinline__ float basis_feat(float v, int q) {
    float u = (v + 1.0f) * 3.5f - (float)q;
    float z = fmaxf(-u * u * L2E, -126.0f);
    return ex2f(z);
}
static __device__ __forceinline__ float silu_feat(float v) {
    float z = fminf(fmaxf(-v * L2E, -126.0f), 126.0f);
    return v * rcpf(1.0f + ex2f(z));
}

static __device__ __forceinline__ void mma8(float* d, const uint4& A, const uint2& B) {
    asm volatile(
        "mma.sync.aligned.m16n8k8.row.col.f32.tf32.tf32.f32 "
        "{%0,%1,%2,%3}, {%4,%5,%6,%7}, {%8,%9}, {%0,%1,%2,%3};"
        : "+f"(d[0]), "+f"(d[1]), "+f"(d[2]), "+f"(d[3])
        : "r"(A.x), "r"(A.y), "r"(A.z), "r"(A.w), "r"(B.x), "r"(B.y));
}

// ------------------------- weight prep kernels ------------------------------
__global__ void prep1(const float* __restrict__ sw, const float* __restrict__ bw) {
    int idx = blockIdx.x * blockDim.x + threadIdx.x;
    if (idx >= KS1 * NT1 * 64) return;
    int r = idx & 1, t = (idx >> 1) & 31, tmp = idx >> 6;
    int nt = tmp % NT1, ks = tmp / NT1;
    int n = nt * 8 + (t >> 2);
    int k = ks * 8 + (t & 3) + r * 4;
    float v = 0.0f;
    if (k < 1568)       v = sw[n * 1568 + k];
    else if (k < 1764)  v = bw[n * 196 + (k - 1568)];
    g_W1[idx] = __uint_as_float(tf32r(v));
}

__global__ void prep2(const float* __restrict__ sw, const float* __restrict__ bw) {
    int idx = blockIdx.x * blockDim.x + threadIdx.x;
    if (idx >= KS2 * NT2 * 64) return;
    int r = idx & 1, t = (idx >> 1) & 31, tmp = idx >> 6;
    int nt = tmp % NT2, ks = tmp / NT2;
    int n = nt * 8 + (t >> 2);           // output p index (padded to 224)
    int k = ks * 8 + (t & 3) + r * 4;
    float v = 0.0f;
    if (n < PP) {
        if (k < 3072)      v = sw[n * 3072 + k];
        else               v = bw[n * 384 + (k - 3072)];
    }
    g_W2[idx] = __uint_as_float(tf32r(v));
}

// ------------------------------ main kernel ---------------------------------
// smem layout (floats):
//   [0, 24640)         region0: xs[196][64] during L1, then h[64][385]
//   [24640, 26688)     As: fragment features, 4 mt * 4 ksL * 32 t * 4 = 2048
//   [26688, 38976)     Bs: weight chunk, up to 4 ksL * 48 nt * 64 = 12288
#define SM_AS   24640
#define SM_BS   26688
#define SM_TOT  38976
#define HSTRIDE 385

__global__ void __launch_bounds__(NTHREADS, 1)
kan_main(const float* __restrict__ x, const float* __restrict__ b1v,
         const float* __restrict__ b2v, float* __restrict__ out) {
    extern __shared__ float smem[];
    float* reg0 = smem;
    float* As   = smem + SM_AS;
    float* Bs   = smem + SM_BS;

    const int m0  = blockIdx.x * MTILE;
    const int b   = m0 / CC;
    const int c0  = m0 % CC;
    const int tid = threadIdx.x;
    const int w    = tid >> 5, lane = tid & 31;
    const int mw   = w & 1;          // row half: rows [mw*32, mw*32+32)
    const int nG   = w >> 1;         // col group 0..3
    const int g    = lane >> 2, t4 = lane & 3;

    // ---- load x slab: xs[p][r] = x[b, p, c0+r] ----
    {
        const float4* xg = reinterpret_cast<const float4*>(x + (size_t)b * PP * CC + c0);
        float4* xs4 = reinterpret_cast<float4*>(reg0);
        for (int i = tid; i < PP * 16; i += NTHREADS) {
            int p = i >> 4, r4 = i & 15;
            xs4[p * 16 + r4] = xg[p * (CC / 4) + r4];
        }
    }
    __syncthreads();

    float acc[2][12][4];
#pragma unroll
    for (int mi = 0; mi < 2; ++mi)
#pragma unroll
        for (int nti = 0; nti < 12; ++nti)
#pragma unroll
            for (int ci = 0; ci < 4; ++ci) acc[mi][nti][ci] = 0.0f;

    // ============================ layer 1 ============================
    for (int kc = 0; kc < K1P / KC; ++kc) {
        const int k0 = kc * KC;
        // stage weight chunk (contiguous in g_W1): 4 ks * 48 nt * 64 = 12288 f
        {
            const float4* wsrc = reinterpret_cast<const float4*>(g_W1 + (size_t)(k0 / 8) * NT1 * 64);
            float4* bdst = reinterpret_cast<float4*>(Bs);
#pragma unroll
            for (int i = 0; i < 12; ++i) bdst[tid + i * NTHREADS] = wsrc[tid + i * NTHREADS];
        }
        // generate feature chunk into fragment layout
#pragma unroll
        for (int i = 0; i < 8; ++i) {
            int idx = tid + i * NTHREADS;      // idx = kL*64 + r
            int r  = idx & 63, kL = idx >> 6;
            int k  = k0 + kL;
            float val = 0.0f;
            if (k < 1568) {
                val = basis_feat(reg0[(k >> 3) * 64 + r], k & 7);
            } else if (k < 1764) {
                val = silu_feat(reg0[(k - 1568) * 64 + r]);
            }
            int mt = r >> 4, rl = r & 15, ksL = kL >> 3, kk = kL & 7;
            int t = ((rl & 7) << 2) | (kk & 3);
            int a = ((kk >> 2) << 1) | (rl >> 3);
            As[(((mt << 2) + ksL) << 7) + (t << 2) + a] = __uint_as_float(tf32r(val));
        }
        __syncthreads();
        // MMA
#pragma unroll
        for (int ksL = 0; ksL < KSL; ++ksL) {
            uint4 Af[2];
#pragma unroll
            for (int mi = 0; mi < 2; ++mi) {
                int mt = mw * 2 + mi;
                Af[mi] = reinterpret_cast<const uint4*>(As)[(mt * 4 + ksL) * 32 + lane];
            }
#pragma unroll
            for (int nti = 0; nti < 12; ++nti) {
                int nt = nG * 12 + nti;
                uint2 Bf = reinterpret_cast<const uint2*>(Bs)[(ksL * NT1 + nt) * 32 + lane];
#pragma unroll
                for (int mi = 0; mi < 2; ++mi) mma8(acc[mi][nti], Af[mi], Bf);
            }
        }
        __syncthreads();
    }

    // ---- h epilogue: h[row][col] = acc + b1[col], stored in reg0 ----
#pragma unroll
    for (int mi = 0; mi < 2; ++mi)
#pragma unroll
        for (int nti = 0; nti < 12; ++nti)
#pragma unroll
            for (int ci = 0; ci < 4; ++ci) {
                int row = mw * 32 + mi * 16 + g + 8 * (ci >> 1);
                int col = nG * 96 + nti * 8 + 2 * t4 + (ci & 1);
                reg0[row * HSTRIDE + col] = acc[mi][nti][ci] + b1v[col];
            }
    __syncthreads();

    // ============================ layer 2 ============================
#pragma unroll
    for (int mi = 0; mi < 2; ++mi)
#pragma unroll
        for (int nti = 0; nti < 7; ++nti)
#pragma unroll
            for (int ci = 0; ci < 4; ++ci) acc[mi][nti][ci] = 0.0f;

    for (int kc = 0; kc < K2 / KC; ++kc) {
        const int k0 = kc * KC;
        {
            const float4* wsrc = reinterpret_cast<const float4*>(g_W2 + (size_t)(k0 / 8) * NT2 * 64);
            float4* bdst = reinterpret_cast<float4*>(Bs);
#pragma unroll
            for (int i = 0; i < 7; ++i) bdst[tid + i * NTHREADS] = wsrc[tid + i * NTHREADS];
        }
#pragma unroll
        for (int i = 0; i < 8; ++i) {
            int idx = tid + i * NTHREADS;
            int r  = idx & 63, kL = idx >> 6;
            int k  = k0 + kL;
            float val;
            if (k < 3072) {
                val = basis_feat(reg0[r * HSTRIDE + (k >> 3)], k & 7);
            } else {
                val = silu_feat(reg0[r * HSTRIDE + (k - 3072)]);
            }
            int mt = r >> 4, rl = r & 15, ksL = kL >> 3, kk = kL & 7;
            int t = ((rl & 7) << 2) | (kk & 3);
            int a = ((kk >> 2) << 1) | (rl >> 3);
            As[(((mt << 2) + ksL) << 7) + (t << 2) + a] = __uint_as_float(tf32r(val));
        }
        __syncthreads();
#pragma unroll
        for (int ksL = 0; ksL < KSL; ++ksL) {
            uint4 Af[2];
#pragma unroll
            for (int mi = 0; mi < 2; ++mi) {
                int mt = mw * 2 + mi;
                Af[mi] = reinterpret_cast<const uint4*>(As)[(mt * 4 + ksL) * 32 + lane];
            }
#pragma unroll
            for (int nti = 0; nti < 7; ++nti) {
                int nt = nG * 7 + nti;
                uint2 Bf = reinterpret_cast<const uint2*>(Bs)[(ksL * NT2 + nt) * 32 + lane];
#pragma unroll
                for (int mi = 0; mi < 2; ++mi) mma8(acc[mi][nti], Af[mi], Bf);
            }
        }
        __syncthreads();
    }

    // ---- epilogue: out[b,p,c0+row] = acc + b2[p] + x[b,p,c0+row] ----
#pragma unroll
    for (int mi = 0; mi < 2; ++mi)
#pragma unroll
        for (int nti = 0; nti < 7; ++nti)
#pragma unroll
            for (int ci = 0; ci < 4; ++ci) {
                int row = mw * 32 + mi * 16 + g + 8 * (ci >> 1);
                int p   = nG * 56 + nti * 8 + 2 * t4 + (ci & 1);
                if (p < PP) {
                    size_t ga = ((size_t)b * PP + p) * CC + c0 + row;
                    out[ga] = acc[mi][nti][ci] + b2v[p] + x[ga];
                }
            }
}

// ------------------------------ launcher ------------------------------------
extern "C" void kernel_launch(void* const* d_in, const int* in_sizes, int n_in,
                              void* d_out, int out_size) {
    (void)in_sizes; (void)n_in; (void)out_size;
    const float* x  = (const float*)d_in[0];
    const float* s1 = (const float*)d_in[1];
    const float* w1 = (const float*)d_in[2];
    const float* b1 = (const float*)d_in[3];
    const float* s2 = (const float*)d_in[4];
    const float* w2 = (const float*)d_in[5];
    const float* b2 = (const float*)d_in[6];
    float* out = (float*)d_out;

    prep1<<<(KS1 * NT1 * 64 + 255) / 256, 256>>>(s1, w1);
    prep2<<<(KS2 * NT2 * 64 + 255) / 256, 256>>>(s2, w2);

    const int smemBytes = SM_TOT * 4;   // 155,904 B
    cudaFuncSetAttribute(kan_main, cudaFuncAttributeMaxDynamicSharedMemorySize, smemBytes);
    kan_main<<<(BQ * CC) / MTILE, NTHREADS, smemBytes>>>(x, b1, b2, out);
}